// round 4
// baseline (speedup 1.0000x reference)
#include <cuda_runtime.h>
#include <cstdint>

#define L_SEQ 1024
#define C_S   1024
#define DD    32      // inner dim
#define CZ    128     // pairwise dim
#define I_PER_CTA 8

// Scratch (allocation-free rule: __device__ globals)
__device__ float g_q[L_SEQ * DD];
__device__ float g_k[L_SEQ * DD];
__device__ float g_Ak[L_SEQ * CZ];

__device__ __forceinline__ unsigned f2tf(float f) {
    unsigned r;
    asm("cvt.rna.tf32.f32 %0, %1;" : "=r"(r) : "f"(f));
    return r;
}

// ---------------------------------------------------------------------------
// Phase 1: LayerNorm + projection -> q,k [L,32]; Ak[i,z] = sum_d k[i,d]*W2[z,d]
// One CTA per sequence row.
// ---------------------------------------------------------------------------
__global__ __launch_bounds__(256) void phase1_kernel(
    const float* __restrict__ x,
    const float* __restrict__ lnw, const float* __restrict__ lnb,
    const float* __restrict__ pw,  const float* __restrict__ pb,
    const float* __restrict__ ow)
{
    __shared__ float s_s[C_S];
    __shared__ float red[16];
    __shared__ float qk[2 * DD];

    const int row = blockIdx.x;
    const int tid = threadIdx.x;
    const int lane = tid & 31;
    const int wid  = tid >> 5;

    // each thread owns 4 contiguous elements
    const float4 xv = ((const float4*)(x + (size_t)row * C_S))[tid];
    float sum = xv.x + xv.y + xv.z + xv.w;
    float sq  = xv.x * xv.x + xv.y * xv.y + xv.z * xv.z + xv.w * xv.w;
#pragma unroll
    for (int o = 16; o; o >>= 1) {
        sum += __shfl_xor_sync(~0u, sum, o);
        sq  += __shfl_xor_sync(~0u, sq,  o);
    }
    if (lane == 0) { red[wid] = sum; red[8 + wid] = sq; }
    __syncthreads();
    sum = 0.f; sq = 0.f;
#pragma unroll
    for (int w = 0; w < 8; w++) { sum += red[w]; sq += red[8 + w]; }
    const float mu   = sum * (1.0f / C_S);
    const float var  = sq * (1.0f / C_S) - mu * mu;
    const float rstd = rsqrtf(var + 1e-5f);

    const float4 wv = ((const float4*)lnw)[tid];
    const float4 bv = ((const float4*)lnb)[tid];
    float4 sv;
    sv.x = (xv.x - mu) * rstd * wv.x + bv.x;
    sv.y = (xv.y - mu) * rstd * wv.y + bv.y;
    sv.z = (xv.z - mu) * rstd * wv.z + bv.z;
    sv.w = (xv.w - mu) * rstd * wv.w + bv.w;
    ((float4*)s_s)[tid] = sv;
    __syncthreads();

    // projection: 64 outputs, warp w computes d = w*8 .. w*8+7
#pragma unroll
    for (int r = 0; r < 8; r++) {
        const int d = wid * 8 + r;
        const float* wr = pw + (size_t)d * C_S;
        float acc = 0.f;
        for (int c = lane; c < C_S; c += 32)
            acc = fmaf(s_s[c], wr[c], acc);
#pragma unroll
        for (int o = 16; o; o >>= 1) acc += __shfl_xor_sync(~0u, acc, o);
        if (lane == 0) qk[d] = acc + pb[d];
    }
    __syncthreads();

    if (tid < DD)            g_q[row * DD + tid]        = qk[tid];
    else if (tid < 2 * DD)   g_k[row * DD + (tid - DD)] = qk[tid];

    if (tid < CZ) {
        float acc = 0.f;
#pragma unroll
        for (int d = 0; d < DD; d++)
            acc = fmaf(qk[DD + d], ow[tid * (2 * DD) + DD + d], acc);
        g_Ak[row * CZ + tid] = acc;   // o_b folded later as bias = ob - Ak
    }
}

// ---------------------------------------------------------------------------
// Phase 2: out[i,j,z] = sum_d q[j,d]*Ghat_i[d,z] + (o_b[z] - Ak[i,z])
//   Ghat_i[d,z] = k[i,d]*W1[z,d] + W2[z,d]   (tf32-rounded, fragment layout)
// Grid: (8 j-tiles of 128, 128 i-groups of I_PER_CTA). 256 threads / CTA.
// Warp w owns j-rows [jbase + 16w, +16); per i: 16 n-tiles x 4 k-steps of
// mma.m16n8k8.tf32, accumulators seeded with the per-i bias.
// ---------------------------------------------------------------------------
__global__ __launch_bounds__(256) void phase2_kernel(
    const float* __restrict__ ow, const float* __restrict__ ob,
    float* __restrict__ out)
{
    // fragment buffer: [kstep(4)][ntile(16)][lane(32)] -> uint2 (b0,b1)
    __shared__ uint2 frag[4 * 16 * 32];
    __shared__ __align__(8) float bias_s[CZ];

    const int tid  = threadIdx.x;
    const int lane = tid & 31;
    const int wid  = tid >> 5;
    const int jbase = blockIdx.x * 128;
    const int ibase = blockIdx.y * I_PER_CTA;

    // ---- Per-thread W preload: 8 fragment pairs owned by this thread ----
    // pair index p = tid + 256*r; decode (kstep, ntile, lane') from p.
    float w1a[8], w1b[8], w2a[8], w2b[8];
#pragma unroll
    for (int r = 0; r < 8; r++) {
        const int p  = tid + 256 * r;
        const int kk = p >> 9;
        const int n  = (p >> 5) & 15;
        const int ln = p & 31;
        const int d0 = (ln & 3) + 8 * kk;
        const int z  = 8 * n + (ln >> 2);
        w1a[r] = ow[z * (2 * DD) + d0];
        w1b[r] = ow[z * (2 * DD) + d0 + 4];
        w2a[r] = ow[z * (2 * DD) + DD + d0];
        w2b[r] = ow[z * (2 * DD) + DD + d0 + 4];
    }

    // ---- A fragments (q side), constant across all i handled by this CTA ----
    const int j0 = jbase + wid * 16 + (lane >> 2);
    unsigned a[4][4];
#pragma unroll
    for (int kk = 0; kk < 4; kk++) {
        const int d = (lane & 3) + 8 * kk;
        a[kk][0] = f2tf(g_q[j0 * DD + d]);
        a[kk][1] = f2tf(g_q[(j0 + 8) * DD + d]);
        a[kk][2] = f2tf(g_q[j0 * DD + d + 4]);
        a[kk][3] = f2tf(g_q[(j0 + 8) * DD + d + 4]);
    }

    const float* bs = bias_s + 2 * (lane & 3);
    const uint2* fp = frag + lane;

    for (int ii = 0; ii < I_PER_CTA; ii++) {
        const int i = ibase + ii;
        __syncthreads();  // previous iteration done reading frag/bias

        if (tid < CZ)
            bias_s[tid] = ob[tid] - g_Ak[i * CZ + tid];

        // build Ghat_i fragments (L1/L2-hot k row, broadcast within warp)
#pragma unroll
        for (int r = 0; r < 8; r++) {
            const int p  = tid + 256 * r;
            const int kk = p >> 9;
            const int d0 = ((p & 3) + 8 * kk);
            const float k0 = g_k[i * DD + d0];
            const float k1 = g_k[i * DD + d0 + 4];
            uint2 v;
            v.x = f2tf(fmaf(k0, w1a[r], w2a[r]));
            v.y = f2tf(fmaf(k1, w1b[r], w2b[r]));
            frag[p] = v;
        }
        __syncthreads();

        float* optr = out + ((size_t)(i * L_SEQ + j0)) * CZ + 2 * (lane & 3);

#pragma unroll
        for (int n = 0; n < 16; n++) {
            const float2 bz = *(const float2*)(bs + 8 * n);
            float c0 = bz.x, c1 = bz.y, c2 = bz.x, c3 = bz.y;
#pragma unroll
            for (int kk = 0; kk < 4; kk++) {
                const uint2 b = fp[(kk * 16 + n) * 32];
                asm volatile(
                    "mma.sync.aligned.m16n8k8.row.col.f32.tf32.tf32.f32 "
                    "{%0,%1,%2,%3},{%4,%5,%6,%7},{%8,%9},{%0,%1,%2,%3};"
                    : "+f"(c0), "+f"(c1), "+f"(c2), "+f"(c3)
                    : "r"(a[kk][0]), "r"(a[kk][1]), "r"(a[kk][2]), "r"(a[kk][3]),
                      "r"(b.x), "r"(b.y));
            }
            float2 o01; o01.x = c0; o01.y = c1;
            float2 o23; o23.x = c2; o23.y = c3;
            *(float2*)(optr + 8 * n)            = o01;   // row j0,   z0..z0+1
            *(float2*)(optr + 8 * n + 8 * CZ)   = o23;   // row j0+8, z0..z0+1
        }
    }
}

// ---------------------------------------------------------------------------
extern "C" void kernel_launch(void* const* d_in, const int* in_sizes, int n_in,
                              void* d_out, int out_size)
{
    const float* x   = (const float*)d_in[0];
    const float* lnw = (const float*)d_in[1];
    const float* lnb = (const float*)d_in[2];
    const float* pw  = (const float*)d_in[3];
    const float* pb  = (const float*)d_in[4];
    const float* ow  = (const float*)d_in[5];
    const float* ob  = (const float*)d_in[6];
    float* out = (float*)d_out;

    phase1_kernel<<<L_SEQ, 256>>>(x, lnw, lnb, pw, pb, ow);
    phase2_kernel<<<dim3(8, L_SEQ / I_PER_CTA), 256>>>(ow, ob, out);
}

// round 5
// speedup vs baseline: 1.0201x; 1.0201x over previous
#include <cuda_runtime.h>
#include <cstdint>

#define L_SEQ 1024
#define C_S   1024
#define DD    32      // inner dim
#define CZ    128     // pairwise dim
#define I_PER_CTA 8
#define R1    4       // rows per CTA in phase1
#define STRIDE 136    // staging row stride in floats; 136 % 32 == 8 -> conflict-free STS.64

// Scratch (allocation-free rule: __device__ globals)
__device__ float g_q[L_SEQ * DD];
__device__ float g_k[L_SEQ * DD];
__device__ float g_Ak[L_SEQ * CZ];

__device__ __forceinline__ unsigned f2tf(float f) {
    unsigned r;
    asm("cvt.rna.tf32.f32 %0, %1;" : "=r"(r) : "f"(f));
    return r;
}

// ---------------------------------------------------------------------------
// Phase 1: LayerNorm + projection -> q,k [L,32]; Ak[i,z] = sum_d k[i,d]*W2[z,d]
// One CTA per R1=4 sequence rows (amortizes the 256KB proj_w read 4x).
// ---------------------------------------------------------------------------
__global__ __launch_bounds__(256) void phase1_kernel(
    const float* __restrict__ x,
    const float* __restrict__ lnw, const float* __restrict__ lnb,
    const float* __restrict__ pw,  const float* __restrict__ pb,
    const float* __restrict__ ow)
{
    __shared__ float4 s4[R1][C_S / 4];   // 16KB normalized rows
    __shared__ float red[2][R1][8];
    __shared__ float qk[R1][2 * DD];

    const int tid  = threadIdx.x;
    const int lane = tid & 31;
    const int wid  = tid >> 5;
    const int row0 = blockIdx.x * R1;

    // ---- LayerNorm stats for 4 rows at once ----
    float4 xv[R1];
    float sum[R1], sq[R1];
#pragma unroll
    for (int r = 0; r < R1; r++) {
        xv[r]  = ((const float4*)(x + (size_t)(row0 + r) * C_S))[tid];
        sum[r] = xv[r].x + xv[r].y + xv[r].z + xv[r].w;
        sq[r]  = fmaf(xv[r].x, xv[r].x, fmaf(xv[r].y, xv[r].y,
                 fmaf(xv[r].z, xv[r].z, xv[r].w * xv[r].w)));
    }
#pragma unroll
    for (int o = 16; o; o >>= 1) {
#pragma unroll
        for (int r = 0; r < R1; r++) {
            sum[r] += __shfl_xor_sync(~0u, sum[r], o);
            sq[r]  += __shfl_xor_sync(~0u, sq[r],  o);
        }
    }
    if (lane == 0) {
#pragma unroll
        for (int r = 0; r < R1; r++) { red[0][r][wid] = sum[r]; red[1][r][wid] = sq[r]; }
    }
    __syncthreads();

    const float4 wv = ((const float4*)lnw)[tid];
    const float4 bv = ((const float4*)lnb)[tid];
#pragma unroll
    for (int r = 0; r < R1; r++) {
        float s = 0.f, q = 0.f;
#pragma unroll
        for (int w = 0; w < 8; w++) { s += red[0][r][w]; q += red[1][r][w]; }
        const float mu   = s * (1.0f / C_S);
        const float var  = q * (1.0f / C_S) - mu * mu;
        const float rstd = rsqrtf(var + 1e-5f);
        float4 sv;
        sv.x = (xv[r].x - mu) * rstd * wv.x + bv.x;
        sv.y = (xv[r].y - mu) * rstd * wv.y + bv.y;
        sv.z = (xv[r].z - mu) * rstd * wv.z + bv.z;
        sv.w = (xv[r].w - mu) * rstd * wv.w + bv.w;
        s4[r][tid] = sv;
    }
    __syncthreads();

    // ---- projection: warp w computes d = w*8 .. w*8+7, 4 rows each ----
#pragma unroll
    for (int rr = 0; rr < 8; rr++) {
        const int d = wid * 8 + rr;
        const float4* wr = (const float4*)(pw + (size_t)d * C_S);
        float a0 = 0.f, a1 = 0.f, a2 = 0.f, a3 = 0.f;
        for (int c = lane; c < C_S / 4; c += 32) {
            const float4 w4 = wr[c];
            const float4 v0 = s4[0][c], v1 = s4[1][c], v2 = s4[2][c], v3 = s4[3][c];
            a0 = fmaf(v0.x, w4.x, fmaf(v0.y, w4.y, fmaf(v0.z, w4.z, fmaf(v0.w, w4.w, a0))));
            a1 = fmaf(v1.x, w4.x, fmaf(v1.y, w4.y, fmaf(v1.z, w4.z, fmaf(v1.w, w4.w, a1))));
            a2 = fmaf(v2.x, w4.x, fmaf(v2.y, w4.y, fmaf(v2.z, w4.z, fmaf(v2.w, w4.w, a2))));
            a3 = fmaf(v3.x, w4.x, fmaf(v3.y, w4.y, fmaf(v3.z, w4.z, fmaf(v3.w, w4.w, a3))));
        }
#pragma unroll
        for (int o = 16; o; o >>= 1) {
            a0 += __shfl_xor_sync(~0u, a0, o);
            a1 += __shfl_xor_sync(~0u, a1, o);
            a2 += __shfl_xor_sync(~0u, a2, o);
            a3 += __shfl_xor_sync(~0u, a3, o);
        }
        if (lane == 0) {
            const float pbd = pb[d];
            qk[0][d] = a0 + pbd; qk[1][d] = a1 + pbd;
            qk[2][d] = a2 + pbd; qk[3][d] = a3 + pbd;
        }
    }
    __syncthreads();

    // ---- scatter q / k ----
    {
        const int r = tid >> 6, v = tid & 63;
        const float val = qk[r][v];
        if (v < DD) g_q[(row0 + r) * DD + v]        = val;
        else        g_k[(row0 + r) * DD + (v - DD)] = val;
    }

    // ---- Ak[i,z] = sum_d k[i,d] * W2[z,d] ----
#pragma unroll
    for (int h = 0; h < 2; h++) {
        const int idx = tid + 256 * h;
        const int r = idx >> 7, z = idx & 127;
        float acc = 0.f;
#pragma unroll
        for (int d = 0; d < DD; d++)
            acc = fmaf(qk[r][DD + d], ow[z * (2 * DD) + DD + d], acc);
        g_Ak[(row0 + r) * CZ + z] = acc;
    }
}

// ---------------------------------------------------------------------------
// Phase 2: out[i,j,z] = sum_d q[j,d]*Ghat_i[d,z] + (o_b[z] - Ak[i,z])
//   Ghat_i[d,z] = k[i,d]*W1[z,d] + W2[z,d]   (tf32-rounded, fragment layout)
// Epilogue stages each warp's 16x128 output tile in padded SMEM (conflict-free)
// and drains with fully coalesced 512B STG.128 warp stores.
// ---------------------------------------------------------------------------
extern __shared__ char smem_dyn[];

__global__ __launch_bounds__(256) void phase2_kernel(
    const float* __restrict__ ow, const float* __restrict__ ob,
    float* __restrict__ out)
{
    uint2*  frag   = (uint2*)smem_dyn;                 // [4*16*32] = 16384B
    float*  bias_s = (float*)(smem_dyn + 16384);       // 512B
    float*  stage  = (float*)(smem_dyn + 16896);       // 8 warps * 16 * STRIDE * 4B

    const int tid  = threadIdx.x;
    const int lane = tid & 31;
    const int wid  = tid >> 5;
    const int jbase = blockIdx.x * 128;
    const int ibase = blockIdx.y * I_PER_CTA;

    // ---- Per-thread W preload: 8 fragment pairs owned by this thread ----
    float w1a[8], w1b[8], w2a[8], w2b[8];
#pragma unroll
    for (int r = 0; r < 8; r++) {
        const int p  = tid + 256 * r;
        const int kk = p >> 9;
        const int n  = (p >> 5) & 15;
        const int ln = p & 31;
        const int d0 = (ln & 3) + 8 * kk;
        const int z  = 8 * n + (ln >> 2);
        w1a[r] = ow[z * (2 * DD) + d0];
        w1b[r] = ow[z * (2 * DD) + d0 + 4];
        w2a[r] = ow[z * (2 * DD) + DD + d0];
        w2b[r] = ow[z * (2 * DD) + DD + d0 + 4];
    }

    // ---- A fragments (q side), constant across all i handled by this CTA ----
    const int j0 = jbase + wid * 16 + (lane >> 2);
    unsigned a[4][4];
#pragma unroll
    for (int kk = 0; kk < 4; kk++) {
        const int d = (lane & 3) + 8 * kk;
        a[kk][0] = f2tf(g_q[j0 * DD + d]);
        a[kk][1] = f2tf(g_q[(j0 + 8) * DD + d]);
        a[kk][2] = f2tf(g_q[j0 * DD + d + 4]);
        a[kk][3] = f2tf(g_q[(j0 + 8) * DD + d + 4]);
    }

    const float* bs = bias_s + 2 * (lane & 3);
    const uint2* fp = frag + lane;

    // staging pointers: row stride 136 floats => STS.64 conflict-free
    float* st = stage + wid * (16 * STRIDE);
    float2* st01 = (float2*)(st + (lane >> 2) * STRIDE + 2 * (lane & 3));
    float2* st23 = (float2*)(st + (8 + (lane >> 2)) * STRIDE + 2 * (lane & 3));
    const float* drain_src = st + 4 * lane;

    for (int ii = 0; ii < I_PER_CTA; ii++) {
        const int i = ibase + ii;
        __syncthreads();  // previous iteration done reading frag/bias (+ stage drained)

        if (tid < CZ)
            bias_s[tid] = ob[tid] - g_Ak[i * CZ + tid];

        // build Ghat_i fragments
#pragma unroll
        for (int r = 0; r < 8; r++) {
            const int p  = tid + 256 * r;
            const int kk = p >> 9;
            const int d0 = ((p & 3) + 8 * kk);
            const float k0 = g_k[i * DD + d0];
            const float k1 = g_k[i * DD + d0 + 4];
            uint2 v;
            v.x = f2tf(fmaf(k0, w1a[r], w2a[r]));
            v.y = f2tf(fmaf(k1, w1b[r], w2b[r]));
            frag[p] = v;
        }
        __syncthreads();

#pragma unroll
        for (int n = 0; n < 16; n++) {
            const float2 bz = *(const float2*)(bs + 8 * n);
            float c0 = bz.x, c1 = bz.y, c2 = bz.x, c3 = bz.y;
#pragma unroll
            for (int kk = 0; kk < 4; kk++) {
                const uint2 b = fp[(kk * 16 + n) * 32];
                asm volatile(
                    "mma.sync.aligned.m16n8k8.row.col.f32.tf32.tf32.f32 "
                    "{%0,%1,%2,%3},{%4,%5,%6,%7},{%8,%9},{%0,%1,%2,%3};"
                    : "+f"(c0), "+f"(c1), "+f"(c2), "+f"(c3)
                    : "r"(a[kk][0]), "r"(a[kk][1]), "r"(a[kk][2]), "r"(a[kk][3]),
                      "r"(b.x), "r"(b.y));
            }
            float2 o01; o01.x = c0; o01.y = c1;
            float2 o23; o23.x = c2; o23.y = c3;
            st01[4 * n] = o01;   // row (lane>>2),     z = 8n + 2*(lane&3)
            st23[4 * n] = o23;   // row 8 + (lane>>2), same z
        }
        __syncwarp();

        // coalesced drain: 16 rows, each warp store = 512B contiguous
        float* dst = out + ((size_t)(i * L_SEQ + jbase + wid * 16)) * CZ + 4 * lane;
#pragma unroll
        for (int t = 0; t < 16; t++) {
            const float4 v = *(const float4*)(drain_src + t * STRIDE);
            *(float4*)(dst + (size_t)t * CZ) = v;
        }
    }
}

// ---------------------------------------------------------------------------
extern "C" void kernel_launch(void* const* d_in, const int* in_sizes, int n_in,
                              void* d_out, int out_size)
{
    const float* x   = (const float*)d_in[0];
    const float* lnw = (const float*)d_in[1];
    const float* lnb = (const float*)d_in[2];
    const float* pw  = (const float*)d_in[3];
    const float* pb  = (const float*)d_in[4];
    const float* ow  = (const float*)d_in[5];
    const float* ob  = (const float*)d_in[6];
    float* out = (float*)d_out;

    const int smem2 = 16384 + 512 + 8 * 16 * STRIDE * 4;  // 86528 B
    cudaFuncSetAttribute(phase2_kernel,
                         cudaFuncAttributeMaxDynamicSharedMemorySize, smem2);

    phase1_kernel<<<L_SEQ / R1, 256>>>(x, lnw, lnb, pw, pb, ow);
    phase2_kernel<<<dim3(8, L_SEQ / I_PER_CTA), 256, smem2>>>(ow, ob, out);
}

// round 6
// speedup vs baseline: 1.1250x; 1.1028x over previous
#include <cuda_runtime.h>
#include <cstdint>

#define L_SEQ 1024
#define C_S   1024
#define DD    32      // inner dim
#define CZ    128     // pairwise dim
#define I_PER_CTA 8
#define R1    8       // rows per CTA in phase1
#define SST   40      // staging row stride (floats); 40%32==8 -> conflict-free

// Scratch (allocation-free rule: __device__ globals)
__device__ float g_q[L_SEQ * DD];
__device__ float g_k[L_SEQ * DD];
__device__ float g_Ak[L_SEQ * CZ];

__device__ __forceinline__ unsigned f2tf(float f) {
    unsigned r;
    asm("cvt.rna.tf32.f32 %0, %1;" : "=r"(r) : "f"(f));
    return r;
}

// ---------------------------------------------------------------------------
// Phase 1: LayerNorm + projection -> q,k [L,32]; Ak[i,z] = sum_d k[i,d]*W2[z,d]
// One CTA per R1=8 rows (amortizes the 256KB proj_w read 8x).
// ---------------------------------------------------------------------------
__global__ __launch_bounds__(256) void phase1_kernel(
    const float* __restrict__ x,
    const float* __restrict__ lnw, const float* __restrict__ lnb,
    const float* __restrict__ pw,  const float* __restrict__ pb,
    const float* __restrict__ ow)
{
    __shared__ float4 s4[R1][C_S / 4];   // 32KB normalized rows
    __shared__ float red[2][R1][8];
    __shared__ float qk[R1][2 * DD];

    const int tid  = threadIdx.x;
    const int lane = tid & 31;
    const int wid  = tid >> 5;
    const int row0 = blockIdx.x * R1;

    // ---- LayerNorm stats for 8 rows ----
    {
        float4 xv[R1];
        float sum[R1], sq[R1];
#pragma unroll
        for (int r = 0; r < R1; r++) {
            xv[r]  = ((const float4*)(x + (size_t)(row0 + r) * C_S))[tid];
            sum[r] = xv[r].x + xv[r].y + xv[r].z + xv[r].w;
            sq[r]  = fmaf(xv[r].x, xv[r].x, fmaf(xv[r].y, xv[r].y,
                     fmaf(xv[r].z, xv[r].z, xv[r].w * xv[r].w)));
        }
#pragma unroll
        for (int o = 16; o; o >>= 1) {
#pragma unroll
            for (int r = 0; r < R1; r++) {
                sum[r] += __shfl_xor_sync(~0u, sum[r], o);
                sq[r]  += __shfl_xor_sync(~0u, sq[r],  o);
            }
        }
        if (lane == 0) {
#pragma unroll
            for (int r = 0; r < R1; r++) { red[0][r][wid] = sum[r]; red[1][r][wid] = sq[r]; }
        }
        __syncthreads();

        const float4 wv = ((const float4*)lnw)[tid];
        const float4 bv = ((const float4*)lnb)[tid];
#pragma unroll
        for (int r = 0; r < R1; r++) {
            float s = 0.f, q = 0.f;
#pragma unroll
            for (int w = 0; w < 8; w++) { s += red[0][r][w]; q += red[1][r][w]; }
            const float mu   = s * (1.0f / C_S);
            const float var  = q * (1.0f / C_S) - mu * mu;
            const float rstd = rsqrtf(var + 1e-5f);
            float4 sv;
            sv.x = (xv[r].x - mu) * rstd * wv.x + bv.x;
            sv.y = (xv[r].y - mu) * rstd * wv.y + bv.y;
            sv.z = (xv[r].z - mu) * rstd * wv.z + bv.z;
            sv.w = (xv[r].w - mu) * rstd * wv.w + bv.w;
            s4[r][tid] = sv;
        }
    }
    __syncthreads();

    // ---- projection: warp w computes d = w*8 .. w*8+7, for 8 rows ----
#pragma unroll
    for (int rr = 0; rr < 8; rr++) {
        const int d = wid * 8 + rr;
        const float4* wr = (const float4*)(pw + (size_t)d * C_S);
        float acc[R1];
#pragma unroll
        for (int r = 0; r < R1; r++) acc[r] = 0.f;
        for (int c = lane; c < C_S / 4; c += 32) {
            const float4 w4 = wr[c];
#pragma unroll
            for (int r = 0; r < R1; r++) {
                const float4 v = s4[r][c];
                acc[r] = fmaf(v.x, w4.x, fmaf(v.y, w4.y,
                         fmaf(v.z, w4.z, fmaf(v.w, w4.w, acc[r]))));
            }
        }
#pragma unroll
        for (int o = 16; o; o >>= 1) {
#pragma unroll
            for (int r = 0; r < R1; r++) acc[r] += __shfl_xor_sync(~0u, acc[r], o);
        }
        if (lane == 0) {
            const float pbd = pb[d];
#pragma unroll
            for (int r = 0; r < R1; r++) qk[r][d] = acc[r] + pbd;
        }
    }
    __syncthreads();

    // ---- scatter q / k (8 rows x 64 values) ----
#pragma unroll
    for (int h = 0; h < 2; h++) {
        const int idx = tid + 256 * h;
        const int r = idx >> 6, v = idx & 63;
        const float val = qk[r][v];
        if (v < DD) g_q[(row0 + r) * DD + v]        = val;
        else        g_k[(row0 + r) * DD + (v - DD)] = val;
    }

    // ---- Ak[i,z] = sum_d k[i,d] * W2[z,d] (8 rows x 128 z) ----
#pragma unroll
    for (int h = 0; h < 4; h++) {
        const int idx = tid + 256 * h;
        const int r = idx >> 7, z = idx & 127;
        float acc = 0.f;
#pragma unroll
        for (int d = 0; d < DD; d++)
            acc = fmaf(qk[r][DD + d], ow[z * (2 * DD) + DD + d], acc);
        g_Ak[(row0 + r) * CZ + z] = acc;
    }
}

// ---------------------------------------------------------------------------
// Phase 2: out[i,j,z] = sum_d q[j,d]*Ghat_i[d,z] + (o_b[z] - Ak[i,z])
//   Ghat_i[d,z] = k[i,d]*W1[z,d] + W2[z,d]   (tf32, fragment layout)
// Chunked epilogue: 4 n-tiles (32 z) staged per warp in a 16x40f buffer,
// drained with full-128B-line STG.128 after each chunk.
// ---------------------------------------------------------------------------
extern __shared__ char smem_dyn[];

__global__ __launch_bounds__(256, 3) void phase2_kernel(
    const float* __restrict__ ow, const float* __restrict__ ob,
    float* __restrict__ out)
{
    uint2*  frag   = (uint2*)smem_dyn;                   // 2048 * 8B  = 16384
    float2* fw2    = (float2*)(smem_dyn + 16384);        // 2048 * 8B  = 16384
    float*  bias_s = (float*)(smem_dyn + 32768);         // 512
    float*  stage  = (float*)(smem_dyn + 33280);         // 8 * 16*40*4 = 20480

    const int tid  = threadIdx.x;
    const int lane = tid & 31;
    const int wid  = tid >> 5;
    const int jbase = blockIdx.x * 128;
    const int ibase = blockIdx.y * I_PER_CTA;

    // ---- W1 pairs in regs; W2 pairs into smem (fragment order) ----
    // pair p = tid + 256*r : kk = r>>1, n = wid + 8*(r&1), lane' = lane
    float w1a[8], w1b[8];
#pragma unroll
    for (int r = 0; r < 8; r++) {
        const int kk = r >> 1;
        const int n  = wid + 8 * (r & 1);
        const int d0 = (lane & 3) + 8 * kk;
        const int z  = 8 * n + (lane >> 2);
        w1a[r] = ow[z * (2 * DD) + d0];
        w1b[r] = ow[z * (2 * DD) + d0 + 4];
        float2 w2;
        w2.x = ow[z * (2 * DD) + DD + d0];
        w2.y = ow[z * (2 * DD) + DD + d0 + 4];
        fw2[tid + 256 * r] = w2;
    }

    // ---- A fragments (q side), constant across all i of this CTA ----
    const int j0 = jbase + wid * 16 + (lane >> 2);
    unsigned a[4][4];
#pragma unroll
    for (int kk = 0; kk < 4; kk++) {
        const int d = (lane & 3) + 8 * kk;
        a[kk][0] = f2tf(g_q[j0 * DD + d]);
        a[kk][1] = f2tf(g_q[(j0 + 8) * DD + d]);
        a[kk][2] = f2tf(g_q[j0 * DD + d + 4]);
        a[kk][3] = f2tf(g_q[(j0 + 8) * DD + d + 4]);
    }

    const uint2* fp = frag + lane;

    // staging pointers (per-warp private 16 x SST floats)
    float* stW = stage + wid * (16 * SST);
    float2* st01 = (float2*)(stW + (lane >> 2) * SST + 2 * (lane & 3));
    float2* st23 = (float2*)(stW + (8 + (lane >> 2)) * SST + 2 * (lane & 3));
    const float* dsrc = stW + (lane >> 3) * SST + (lane & 7) * 4;

    for (int ii = 0; ii < I_PER_CTA; ii++) {
        const int i = ibase + ii;
        __syncthreads();  // frag/bias consumers of previous i are done

        if (tid < CZ)
            bias_s[tid] = ob[tid] - g_Ak[i * CZ + tid];

        // build Ghat_i fragments: k row is L1/L2-hot broadcast
        {
            float klo[4], khi[4];
#pragma unroll
            for (int kk = 0; kk < 4; kk++) {
                const int d0 = (lane & 3) + 8 * kk;
                klo[kk] = g_k[i * DD + d0];
                khi[kk] = g_k[i * DD + d0 + 4];
            }
#pragma unroll
            for (int r = 0; r < 8; r++) {
                const int kk = r >> 1;
                const float2 w2 = fw2[tid + 256 * r];
                uint2 v;
                v.x = f2tf(fmaf(klo[kk], w1a[r], w2.x));
                v.y = f2tf(fmaf(khi[kk], w1b[r], w2.y));
                frag[tid + 256 * r] = v;
            }
        }
        __syncthreads();

        // base output pointer for this warp's j-stripe
        float* obase = out + ((size_t)(i * L_SEQ + jbase + wid * 16 + (lane >> 3))) * CZ
                           + (lane & 7) * 4;

#pragma unroll
        for (int c = 0; c < 4; c++) {
#pragma unroll
            for (int nl = 0; nl < 4; nl++) {
                const int n = 4 * c + nl;
                const float2 bz = *(const float2*)(bias_s + 8 * n + 2 * (lane & 3));
                float c0 = bz.x, c1 = bz.y, c2 = bz.x, c3 = bz.y;
#pragma unroll
                for (int kk = 0; kk < 4; kk++) {
                    const uint2 b = fp[(kk * 16 + n) * 32];
                    asm volatile(
                        "mma.sync.aligned.m16n8k8.row.col.f32.tf32.tf32.f32 "
                        "{%0,%1,%2,%3},{%4,%5,%6,%7},{%8,%9},{%0,%1,%2,%3};"
                        : "+f"(c0), "+f"(c1), "+f"(c2), "+f"(c3)
                        : "r"(a[kk][0]), "r"(a[kk][1]), "r"(a[kk][2]), "r"(a[kk][3]),
                          "r"(b.x), "r"(b.y));
                }
                float2 o01; o01.x = c0; o01.y = c1;
                float2 o23; o23.x = c2; o23.y = c3;
                st01[4 * nl] = o01;   // row (lane>>2),   z = 32c + 8nl + 2*(lane&3)
                st23[4 * nl] = o23;   // row 8+(lane>>2)
            }
            __syncwarp();
            // drain chunk: 16 rows x 32 z; each STG.128 = 4 full 128B lines
            float* dst = obase + c * 32;
#pragma unroll
            for (int t = 0; t < 4; t++) {
                const float4 v = *(const float4*)(dsrc + t * 4 * SST);
                *(float4*)(dst + (size_t)t * 4 * CZ) = v;
            }
            __syncwarp();
        }
    }
}

// ---------------------------------------------------------------------------
extern "C" void kernel_launch(void* const* d_in, const int* in_sizes, int n_in,
                              void* d_out, int out_size)
{
    const float* x   = (const float*)d_in[0];
    const float* lnw = (const float*)d_in[1];
    const float* lnb = (const float*)d_in[2];
    const float* pw  = (const float*)d_in[3];
    const float* pb  = (const float*)d_in[4];
    const float* ow  = (const float*)d_in[5];
    const float* ob  = (const float*)d_in[6];
    float* out = (float*)d_out;

    const int smem2 = 16384 + 16384 + 512 + 8 * 16 * SST * 4;  // 53760 B
    cudaFuncSetAttribute(phase2_kernel,
                         cudaFuncAttributeMaxDynamicSharedMemorySize, smem2);

    phase1_kernel<<<L_SEQ / R1, 256>>>(x, lnw, lnb, pw, pb, ow);
    phase2_kernel<<<dim3(8, L_SEQ / I_PER_CTA), 256, smem2>>>(ow, ob, out);
}